// round 1
// baseline (speedup 1.0000x reference)
#include <cuda_runtime.h>

#define BS 4
#define H0 64
#define W0 64
#define L0 4096   /* H0*W0 */
#define L1 4096
#define NM 20000  /* number of candidate matches */
#define ANUM 64   /* anchors per batch */

// Scratch: per-cell winning match index (last-write-wins emulation of jax scatter).
__device__ int g_winner[BS * L0];

__global__ void init_winner_kernel() {
    int i = blockIdx.x * blockDim.x + threadIdx.x;
    if (i < BS * L0) g_winner[i] = -1;
}

__global__ void scatter_kernel(const int* __restrict__ b_ids,
                               const int* __restrict__ i_ids) {
    int m = blockIdx.x * blockDim.x + threadIdx.x;
    if (m < NM) {
        // last update (largest m) wins -> atomicMax on the match index
        atomicMax(&g_winner[b_ids[m] * L0 + i_ids[m]], m);
    }
}

// One block per batch, 1024 threads; each thread owns 4 raster-contiguous cells.
__global__ void __launch_bounds__(1024) anchors_kernel(
    const float* __restrict__ mconf,
    const int* __restrict__ j_ids,
    float* __restrict__ out /* [BS, ANUM, 2, 2] */) {

    __shared__ float sconf[L0];
    __shared__ int s_sel_i[ANUM];
    __shared__ int s_sel_j[ANUM];
    __shared__ int s_warp[32];
    __shared__ int s_total;

    const int b = blockIdx.x;
    const int t = threadIdx.x;

    // Gather conf grid for this batch from winners
    for (int c = t; c < L0; c += 1024) {
        int w = g_winner[b * L0 + c];
        sconf[c] = (w >= 0) ? mconf[w] : 0.0f;
    }
    __syncthreads();

    // NMS mask for 4 raster-contiguous cells:
    // survivor <=> v > 0 and v >= right, down, diag neighbors (pad=0)
    const int base = t * 4;
    int lmask = 0;
    int cnt = 0;
#pragma unroll
    for (int k = 0; k < 4; k++) {
        int c = base + k;
        int h = c >> 6, w = c & 63;
        float v = sconf[c];
        bool ok = v > 0.0f;
        if (ok && (w + 1 < W0))                 ok = (v >= sconf[c + 1]);
        if (ok && (h + 1 < H0))                 ok = (v >= sconf[c + 64]);
        if (ok && (w + 1 < W0) && (h + 1 < H0)) ok = (v >= sconf[c + 65]);
        if (ok) { lmask |= (1 << k); cnt++; }
    }

    // Block-wide exclusive scan of survivor counts (thread order == raster order)
    const int lane = t & 31, warp = t >> 5;
    int incl = cnt;
#pragma unroll
    for (int d = 1; d < 32; d <<= 1) {
        int n = __shfl_up_sync(0xffffffffu, incl, d);
        if (lane >= d) incl += n;
    }
    if (lane == 31) s_warp[warp] = incl;
    __syncthreads();
    if (warp == 0) {
        int v = s_warp[lane];
#pragma unroll
        for (int d = 1; d < 32; d <<= 1) {
            int n = __shfl_up_sync(0xffffffffu, v, d);
            if (lane >= d) v += n;
        }
        s_warp[lane] = v;
        if (lane == 31) s_total = v;
    }
    __syncthreads();
    int excl = incl - cnt + (warp > 0 ? s_warp[warp - 1] : 0);

    // Record the first ANUM survivors (raster order) with their j targets
    if (lmask) {
        int r = excl;
#pragma unroll
        for (int k = 0; k < 4; k++) {
            if (lmask & (1 << k)) {
                if (r < ANUM) {
                    int c = base + k;
                    s_sel_i[r] = c;
                    int w = g_winner[b * L0 + c];
                    s_sel_j[r] = j_ids[w];
                }
                r++;
            }
        }
    }
    __syncthreads();

    // Emit anchors [ANUM, 2, 2] for this batch
    if (t < ANUM) {
        int total = s_total;
        float4 res;
        if (total == 0) {
            res = make_float4(0.0f, 0.0f, 0.0f, 0.0f);
        } else {
            int idx = t % total;          // t<64: always < min(total, 64) -> stored
            int i_sel = s_sel_i[idx];
            int j_sel = s_sel_j[idx];
            res.x = (float)(i_sel >> 6);  // i // W0
            res.y = (float)(i_sel & 63);  // i %  W0
            res.z = (float)(j_sel >> 6);  // j // W1
            res.w = (float)(j_sel & 63);  // j %  W1
        }
        reinterpret_cast<float4*>(out)[b * ANUM + t] = res;
    }
}

extern "C" void kernel_launch(void* const* d_in, const int* in_sizes, int n_in,
                              void* d_out, int out_size) {
    const float* conf_matrix = (const float*)d_in[0];
    const float* mconf       = (const float*)d_in[1];
    const int*   b_ids       = (const int*)d_in[2];
    const int*   i_ids       = (const int*)d_in[3];
    const int*   j_ids       = (const int*)d_in[4];
    float* out = (float*)d_out;

    init_winner_kernel<<<(BS * L0 + 255) / 256, 256>>>();
    scatter_kernel<<<(NM + 255) / 256, 256>>>(b_ids, i_ids);
    anchors_kernel<<<BS, 1024>>>(mconf, j_ids, out);

    // conf_matrix passes through unchanged: bulk D2D copy after the 1024 anchor floats
    const size_t conf_bytes = (size_t)BS * L0 * L1 * sizeof(float);
    cudaMemcpyAsync(out + (size_t)BS * ANUM * 4, conf_matrix, conf_bytes,
                    cudaMemcpyDeviceToDevice, 0);
}